// round 1
// baseline (speedup 1.0000x reference)
#include <cuda_runtime.h>

#define NROWS 16384
#define INDIM 768
#define DD    128

// ---------------- device scratch (no allocs allowed) ----------------
__device__ float g_wvfc[DD];          // W_v @ W_fc   [128]
__device__ float g_bu_p;              // b_v @ W_fc
__device__ float g_bu;                // full u bias
__device__ float g_wqk[INDIM * 256];  // W_token @ W_qkv[:, :256]   [768,256]
__device__ float g_wu[INDIM];         // W_token @ wvfc             [768]
__device__ float g_bqk[256];          // b_token @ W_qkv[:, :256] + b_qkv[:256]
__device__ float g_q[NROWS * DD];
__device__ float g_k[NROWS * DD];
__device__ float g_u[NROWS];

// ---------------- f32x2 helpers (FFMA2 only reachable via PTX) -------
__device__ __forceinline__ unsigned long long ffma2(unsigned long long a,
                                                    unsigned long long b,
                                                    unsigned long long c) {
    unsigned long long d;
    asm("fma.rn.f32x2 %0, %1, %2, %3;" : "=l"(d) : "l"(a), "l"(b), "l"(c));
    return d;
}
__device__ __forceinline__ void unpack2(unsigned long long v, float& lo, float& hi) {
    asm("mov.b64 {%0, %1}, %2;" : "=f"(lo), "=f"(hi) : "l"(v));
}

// ---------------- P1: wvfc[d] = sum_e Wqkv[d][2D+e]*Wfc[e] ----------
__global__ void k_p1(const float* __restrict__ W_qkv, const float* __restrict__ W_fc,
                     const float* __restrict__ b_qkv) {
    int d = threadIdx.x;  // 128
    float acc = 0.f;
    for (int e = 0; e < DD; e++) acc += W_qkv[d * 3 * DD + 2 * DD + e] * W_fc[e];
    g_wvfc[d] = acc;
    if (d == 0) {
        float b = 0.f;
        for (int e = 0; e < DD; e++) b += b_qkv[2 * DD + e] * W_fc[e];
        g_bu_p = b;
    }
}

// ---------------- P2: Wqk[t][n] = sum_d Wt[t][d]*Wqkv[d][n]; wu[t] ---
__global__ void k_p2(const float* __restrict__ W_token, const float* __restrict__ W_qkv) {
    __shared__ float wt[DD];
    int t = blockIdx.x;   // 768
    int n = threadIdx.x;  // 256
    if (n < DD) wt[n] = W_token[t * DD + n];
    __syncthreads();
    float acc = 0.f;
    for (int d = 0; d < DD; d++) acc += wt[d] * W_qkv[d * 3 * DD + n];
    g_wqk[t * 256 + n] = acc;
    if (n == 0) {
        float a = 0.f;
        for (int d = 0; d < DD; d++) a += wt[d] * g_wvfc[d];
        g_wu[t] = a;
    }
}

// ---------------- P3: biases ----------------------------------------
__global__ void k_p3(const float* __restrict__ b_token, const float* __restrict__ W_qkv,
                     const float* __restrict__ b_qkv) {
    int n = threadIdx.x;  // 256
    float acc = 0.f;
    for (int d = 0; d < DD; d++) acc += b_token[d] * W_qkv[d * 3 * DD + n];
    g_bqk[n] = acc + b_qkv[n];
    if (n == 0) {
        float a = 0.f;
        for (int d = 0; d < DD; d++) a += b_token[d] * g_wvfc[d];
        g_bu = a + g_bu_p;
    }
}

// ---------------- projection GEMM: [16384,768]@[768,256] -> q,k ------
// grid (128 row-tiles, 2 halves), block 256, BM=BN=128, BK=16, TM=TN=8
#define PB_BK 16
__global__ __launch_bounds__(256) void k_proj(const float* __restrict__ x) {
    __shared__ float As[PB_BK][128];  // [t][m]
    __shared__ float Bs[PB_BK][128];  // [t][n]
    int tid = threadIdx.x;
    int tx = tid % 16, ty = tid / 16;
    int row0 = blockIdx.x * 128;
    int half = blockIdx.y;  // 0 -> q, 1 -> k
    const float* Wcol = g_wqk + half * DD;  // row stride 256

    float acc[8][8];
#pragma unroll
    for (int i = 0; i < 8; i++)
#pragma unroll
        for (int j = 0; j < 8; j++) acc[i][j] = 0.f;

    for (int kc = 0; kc < INDIM; kc += PB_BK) {
        // x tile: 128 rows x 16 k (512 float4)
#pragma unroll
        for (int i = 0; i < 2; i++) {
            int idx = tid + i * 256;
            int r = idx >> 2, c4 = idx & 3;
            float4 v = *(const float4*)(x + (row0 + r) * INDIM + kc + c4 * 4);
            As[c4 * 4 + 0][r] = v.x; As[c4 * 4 + 1][r] = v.y;
            As[c4 * 4 + 2][r] = v.z; As[c4 * 4 + 3][r] = v.w;
        }
        // W tile: 16 t x 128 n
#pragma unroll
        for (int i = 0; i < 2; i++) {
            int idx = tid + i * 256;
            int tt = idx >> 5, c4 = idx & 31;
            float4 v = *(const float4*)(Wcol + (kc + tt) * 256 + c4 * 4);
            *(float4*)&Bs[tt][c4 * 4] = v;
        }
        __syncthreads();
#pragma unroll
        for (int t = 0; t < PB_BK; t++) {
            float a[8], b[8];
            *(float4*)&a[0] = *(float4*)&As[t][ty * 8];
            *(float4*)&a[4] = *(float4*)&As[t][ty * 8 + 4];
            *(float4*)&b[0] = *(float4*)&Bs[t][tx * 8];
            *(float4*)&b[4] = *(float4*)&Bs[t][tx * 8 + 4];
#pragma unroll
            for (int i = 0; i < 8; i++)
#pragma unroll
                for (int j = 0; j < 8; j++) acc[i][j] = fmaf(a[i], b[j], acc[i][j]);
        }
        __syncthreads();
    }
    float* dst = half ? g_k : g_q;
#pragma unroll
    for (int i = 0; i < 8; i++) {
        int r = row0 + ty * 8 + i;
#pragma unroll
        for (int j = 0; j < 8; j += 4) {
            int n = tx * 8 + j;
            float4 v;
            v.x = acc[i][j + 0] + g_bqk[half * DD + n + 0];
            v.y = acc[i][j + 1] + g_bqk[half * DD + n + 1];
            v.z = acc[i][j + 2] + g_bqk[half * DD + n + 2];
            v.w = acc[i][j + 3] + g_bqk[half * DD + n + 3];
            *(float4*)(dst + r * DD + n) = v;
        }
    }
}

// ---------------- u matvec: u[i] = x[i]·wu + bu ----------------------
__global__ void k_u(const float* __restrict__ x) {
    int w = (blockIdx.x * blockDim.x + threadIdx.x) >> 5;
    int lane = threadIdx.x & 31;
    if (w >= NROWS) return;
    const float* xr = x + (long)w * INDIM;
    float acc = 0.f;
    for (int t = lane; t < INDIM; t += 32) acc += xr[t] * g_wu[t];
#pragma unroll
    for (int off = 16; off; off >>= 1) acc += __shfl_xor_sync(0xFFFFFFFFu, acc, off);
    if (lane == 0) g_u[w] = acc + g_bu;
}

// ---------------- attention: out_i = sum_j sigmoid(q_i·k_j) u_j ------
// grid 128 (BM=128 row tiles), block 256 (16x16), BN=128, full D in smem.
// f32x2 over the d dimension; strided (stride-16) ownership + pad-2 rows
// for conflict-free LDS.64.
#define AT_LD (DD + 2)                                     // 130 floats/row
#define AT_SMEM ((2 * 128 * AT_LD + 128) * (int)sizeof(float))
__global__ __launch_bounds__(256, 1) void k_attn(const float* __restrict__ b_fc,
                                                 float* __restrict__ out) {
    extern __shared__ float smem[];
    float* Qs = smem;                    // 128 x 130
    float* Ks = smem + 128 * AT_LD;      // 128 x 130
    float* Us = smem + 2 * 128 * AT_LD;  // 128
    int tid = threadIdx.x;
    int tx = tid % 16, ty = tid / 16;
    int row0 = blockIdx.x * 128;

    // load Q tile once (float2, row stride 130 keeps 8B alignment)
    for (int i = tid; i < 128 * (DD / 2); i += 256) {
        int r = i >> 6, c = (i & 63) * 2;
        *(float2*)&Qs[r * AT_LD + c] = *(const float2*)(g_q + (row0 + r) * DD + c);
    }

    float o[8];
#pragma unroll
    for (int m = 0; m < 8; m++) o[m] = 0.f;

    for (int jt = 0; jt < NROWS / 128; jt++) {
        __syncthreads();  // previous compute done before overwriting Ks
        int j0 = jt * 128;
        for (int i = tid; i < 128 * (DD / 2); i += 256) {
            int r = i >> 6, c = (i & 63) * 2;
            *(float2*)&Ks[r * AT_LD + c] = *(const float2*)(g_k + (j0 + r) * DD + c);
        }
        if (tid < 128) Us[tid] = g_u[j0 + tid];
        __syncthreads();

        unsigned long long acc[8][8];
#pragma unroll
        for (int m = 0; m < 8; m++)
#pragma unroll
            for (int n = 0; n < 8; n++) acc[m][n] = 0ULL;

#pragma unroll 4
        for (int d = 0; d < DD; d += 2) {
            unsigned long long a2[8], b2[8];
#pragma unroll
            for (int m = 0; m < 8; m++)
                a2[m] = *(const unsigned long long*)&Qs[(ty + m * 16) * AT_LD + d];
#pragma unroll
            for (int n = 0; n < 8; n++)
                b2[n] = *(const unsigned long long*)&Ks[(tx + n * 16) * AT_LD + d];
#pragma unroll
            for (int m = 0; m < 8; m++)
#pragma unroll
                for (int n = 0; n < 8; n++) acc[m][n] = ffma2(a2[m], b2[n], acc[m][n]);
        }

        // sigmoid + weighted row accumulate
#pragma unroll
        for (int n = 0; n < 8; n++) {
            float un = Us[tx + n * 16];
#pragma unroll
            for (int m = 0; m < 8; m++) {
                float lo, hi;
                unpack2(acc[m][n], lo, hi);
                float s = lo + hi;
                float e = __expf(-s);
                float sg = __fdividef(1.0f, 1.0f + e);
                o[m] = fmaf(sg, un, o[m]);
            }
        }
    }

    // cross-thread (tx) reduction per row via smem
    __syncthreads();
    float* red = smem;  // 128 x 16
#pragma unroll
    for (int m = 0; m < 8; m++) red[(ty + m * 16) * 16 + tx] = o[m];
    __syncthreads();
    if (tid < 128) {
        float s = 0.f;
#pragma unroll
        for (int t = 0; t < 16; t++) s += red[tid * 16 + t];
        out[row0 + tid] = s + b_fc[0];
    }
}

// ---------------- launch ---------------------------------------------
extern "C" void kernel_launch(void* const* d_in, const int* in_sizes, int n_in,
                              void* d_out, int out_size) {
    const float* x       = (const float*)d_in[0];
    // d_in[1] = decay_value (unused by the reference computation)
    const float* W_token = (const float*)d_in[2];
    const float* b_token = (const float*)d_in[3];
    const float* W_qkv   = (const float*)d_in[4];
    const float* b_qkv   = (const float*)d_in[5];
    const float* W_fc    = (const float*)d_in[6];
    const float* b_fc    = (const float*)d_in[7];
    float* out = (float*)d_out;

    cudaFuncSetAttribute(k_attn, cudaFuncAttributeMaxDynamicSharedMemorySize, AT_SMEM);

    k_p1<<<1, 128>>>(W_qkv, W_fc, b_qkv);
    k_p2<<<768, 256>>>(W_token, W_qkv);
    k_p3<<<1, 256>>>(b_token, W_qkv, b_qkv);
    k_proj<<<dim3(128, 2), 256>>>(x);
    k_u<<<NROWS / 8, 256>>>(x);
    k_attn<<<128, 256, AT_SMEM>>>(b_fc, out);
}

// round 6
// speedup vs baseline: 2.8239x; 2.8239x over previous
#include <cuda_runtime.h>
#include <cuda_bf16.h>
#include <cstdint>

#define NROWS 16384
#define INDIM 768
#define DD    128
#define BN    128
#define NJT   (NROWS / BN)

// ---------------- device scratch (no allocs allowed) ----------------
__device__ float g_wvfc[DD];
__device__ float g_bu_p;
__device__ float g_bu;
__device__ float g_wqk[INDIM * 256];
__device__ float g_wu[INDIM];
__device__ float g_bqk[256];
__device__ float g_u[NROWS];
__device__ __align__(16) __nv_bfloat16 g_qhi[NROWS * DD];
__device__ __align__(16) __nv_bfloat16 g_qlo[NROWS * DD];
__device__ __align__(16) __nv_bfloat16 g_khi[NROWS * DD];
__device__ __align__(16) __nv_bfloat16 g_klo[NROWS * DD];

// ---------------- PTX helpers (base ISA only: sm_80-class) -----------
__device__ __forceinline__ uint32_t smem_u32(const void* p) {
    uint32_t a;
    asm("{ .reg .u64 t; cvta.to.shared.u64 t, %1; cvt.u32.u64 %0, t; }" : "=r"(a) : "l"(p));
    return a;
}
#define CP_ASYNC16(dst, src) asm volatile("cp.async.cg.shared.global [%0], [%1], 16;" :: "r"(dst), "l"(src) : "memory")
#define CP_COMMIT()          asm volatile("cp.async.commit_group;" ::: "memory")
#define CP_WAIT(n)           asm volatile("cp.async.wait_group %0;" :: "n"(n) : "memory")

__device__ __forceinline__ void ldsm4(uint32_t* r, uint32_t addr) {
    asm volatile("ldmatrix.sync.aligned.m8n8.x4.shared.b16 {%0,%1,%2,%3}, [%4];"
                 : "=r"(r[0]), "=r"(r[1]), "=r"(r[2]), "=r"(r[3]) : "r"(addr));
}
__device__ __forceinline__ void mma_bf16(float* c, const uint32_t* a, const uint32_t* b) {
    asm volatile("mma.sync.aligned.m16n8k16.row.col.f32.bf16.bf16.f32 "
                 "{%0,%1,%2,%3}, {%4,%5,%6,%7}, {%8,%9}, {%0,%1,%2,%3};"
                 : "+f"(c[0]), "+f"(c[1]), "+f"(c[2]), "+f"(c[3])
                 : "r"(a[0]), "r"(a[1]), "r"(a[2]), "r"(a[3]), "r"(b[0]), "r"(b[1]));
}
__device__ __forceinline__ float tanh_ap(float x) {
    float r;
    asm("tanh.approx.f32 %0, %1;" : "=f"(r) : "f"(x));
    return r;
}

// ---------------- P1/P2/P3: tiny weight precompute --------------------
__global__ void k_p1(const float* __restrict__ W_qkv, const float* __restrict__ W_fc,
                     const float* __restrict__ b_qkv) {
    int d = threadIdx.x;
    float acc = 0.f;
    for (int e = 0; e < DD; e++) acc += W_qkv[d * 3 * DD + 2 * DD + e] * W_fc[e];
    g_wvfc[d] = acc;
    if (d == 0) {
        float b = 0.f;
        for (int e = 0; e < DD; e++) b += b_qkv[2 * DD + e] * W_fc[e];
        g_bu_p = b;
    }
}
__global__ void k_p2(const float* __restrict__ W_token, const float* __restrict__ W_qkv) {
    __shared__ float wt[DD];
    int t = blockIdx.x, n = threadIdx.x;
    if (n < DD) wt[n] = W_token[t * DD + n];
    __syncthreads();
    float acc = 0.f;
    for (int d = 0; d < DD; d++) acc += wt[d] * W_qkv[d * 3 * DD + n];
    g_wqk[t * 256 + n] = acc;
    if (n == 0) {
        float a = 0.f;
        for (int d = 0; d < DD; d++) a += wt[d] * g_wvfc[d];
        g_wu[t] = a;
    }
}
__global__ void k_p3(const float* __restrict__ b_token, const float* __restrict__ W_qkv,
                     const float* __restrict__ b_qkv) {
    int n = threadIdx.x;
    float acc = 0.f;
    for (int d = 0; d < DD; d++) acc += b_token[d] * W_qkv[d * 3 * DD + n];
    g_bqk[n] = acc + b_qkv[n];
    if (n == 0) {
        float a = 0.f;
        for (int d = 0; d < DD; d++) a += b_token[d] * g_wvfc[d];
        g_bu = a + g_bu_p;
    }
}

// ---------------- projection GEMM -> bf16 hi/lo split ------------------
#define PB_BK 16
__global__ __launch_bounds__(256) void k_proj(const float* __restrict__ x) {
    __shared__ float As[PB_BK][128];
    __shared__ float Bs[PB_BK][128];
    int tid = threadIdx.x;
    int tx = tid % 16, ty = tid / 16;
    int row0 = blockIdx.x * 128;
    int half = blockIdx.y;
    const float* Wcol = g_wqk + half * DD;

    float acc[8][8];
#pragma unroll
    for (int i = 0; i < 8; i++)
#pragma unroll
        for (int j = 0; j < 8; j++) acc[i][j] = 0.f;

    for (int kc = 0; kc < INDIM; kc += PB_BK) {
#pragma unroll
        for (int i = 0; i < 2; i++) {
            int idx = tid + i * 256;
            int r = idx >> 2, c4 = idx & 3;
            float4 v = *(const float4*)(x + (row0 + r) * INDIM + kc + c4 * 4);
            As[c4 * 4 + 0][r] = v.x; As[c4 * 4 + 1][r] = v.y;
            As[c4 * 4 + 2][r] = v.z; As[c4 * 4 + 3][r] = v.w;
        }
#pragma unroll
        for (int i = 0; i < 2; i++) {
            int idx = tid + i * 256;
            int tt = idx >> 5, c4 = idx & 31;
            float4 v = *(const float4*)(Wcol + (kc + tt) * 256 + c4 * 4);
            *(float4*)&Bs[tt][c4 * 4] = v;
        }
        __syncthreads();
#pragma unroll
        for (int t = 0; t < PB_BK; t++) {
            float a[8], b[8];
            *(float4*)&a[0] = *(float4*)&As[t][ty * 8];
            *(float4*)&a[4] = *(float4*)&As[t][ty * 8 + 4];
            *(float4*)&b[0] = *(float4*)&Bs[t][tx * 8];
            *(float4*)&b[4] = *(float4*)&Bs[t][tx * 8 + 4];
#pragma unroll
            for (int i = 0; i < 8; i++)
#pragma unroll
                for (int j = 0; j < 8; j++) acc[i][j] = fmaf(a[i], b[j], acc[i][j]);
        }
        __syncthreads();
    }
    __nv_bfloat16* dhi = half ? g_khi : g_qhi;
    __nv_bfloat16* dlo = half ? g_klo : g_qlo;
#pragma unroll
    for (int i = 0; i < 8; i++) {
        int r = row0 + ty * 8 + i;
        __nv_bfloat16 hi8[8], lo8[8];
#pragma unroll
        for (int j = 0; j < 8; j++) {
            int n = tx * 8 + j;
            float v = acc[i][j] + g_bqk[half * DD + n];
            __nv_bfloat16 h = __float2bfloat16(v);
            hi8[j] = h;
            lo8[j] = __float2bfloat16(v - __bfloat162float(h));
        }
        *(uint4*)(dhi + r * DD + tx * 8) = *(uint4*)hi8;
        *(uint4*)(dlo + r * DD + tx * 8) = *(uint4*)lo8;
    }
}

// ---------------- u matvec --------------------------------------------
__global__ void k_u(const float* __restrict__ x) {
    int w = (blockIdx.x * blockDim.x + threadIdx.x) >> 5;
    int lane = threadIdx.x & 31;
    if (w >= NROWS) return;
    const float* xr = x + (long)w * INDIM;
    float acc = 0.f;
    for (int t = lane; t < INDIM; t += 32) acc += xr[t] * g_wu[t];
#pragma unroll
    for (int off = 16; off; off >>= 1) acc += __shfl_xor_sync(0xFFFFFFFFu, acc, off);
    if (lane == 0) g_u[w] = acc + g_bu;
}

// ---------------- attention: HMMA bf16x3 QK^T + sigmoid epilogue -------
// Smem: two K buffers (hi 32KB + lo 32KB each) = 128KB; Q staged into buf1
// then consumed into register fragments. u tile 512B.
// Tile layout: row-major 128 rows x 256B, 16B units XOR-swizzled by (row&7).
#define KBUF   65536
#define SO_US  131072
#define AT_SMEM (SO_US + 512)

__global__ __launch_bounds__(256, 1) void k_attn(const float* __restrict__ b_fc,
                                                 float* __restrict__ out) {
    extern __shared__ char smem[];
    uint32_t sb = smem_u32(smem);
    int tid = threadIdx.x, lane = tid & 31, w = tid >> 5;
    int row0 = blockIdx.x * 128;
    float* Us = (float*)(smem + SO_US);

    // stage K tile 0 -> buf0, Q tile -> buf1 (hi & lo components)
#pragma unroll
    for (int t = 0; t < 8; t++) {
        int idx = t * 256 + tid;
        int r = idx >> 4, cu = idx & 15;
        uint32_t off = (uint32_t)r * 256u + (uint32_t)((cu ^ (r & 7)) << 4);
        CP_ASYNC16(sb + off,                 g_khi + r * DD + cu * 8);
        CP_ASYNC16(sb + 32768 + off,         g_klo + r * DD + cu * 8);
        CP_ASYNC16(sb + KBUF + off,          g_qhi + (row0 + r) * DD + cu * 8);
        CP_ASYNC16(sb + KBUF + 32768 + off,  g_qlo + (row0 + r) * DD + cu * 8);
    }
    CP_COMMIT();
    CP_WAIT(0);
    __syncthreads();

    // extract Q fragments (warp w owns rows 16w..16w+15)
    uint32_t Ahi[8][4], Alo[8][4];
    {
        int rA = 16 * w + (lane & 15);
        int cuA = lane >> 4;  // 0..1 (k-half)
        uint32_t rb = (uint32_t)rA * 256u;
        int xA = rA & 7;
#pragma unroll
        for (int kk = 0; kk < 8; kk++) {
            uint32_t off = rb + (uint32_t)(((kk * 2 + cuA) ^ xA) << 4);
            ldsm4(Ahi[kk], sb + KBUF + off);
            ldsm4(Alo[kk], sb + KBUF + 32768 + off);
        }
    }
    __syncthreads();  // Q staging area now reusable as K buf1

    // per-lane B ldmatrix address parts (x4 covers n-block pair)
    int rB = (lane & 7) + ((lane & 16) >> 1);  // n row within 16-row pair
    int cB = (lane >> 3) & 1;                  // k-half
    uint32_t uB = (uint32_t)rB * 256u;
    int xB = rB & 7;

    float o0 = 0.f, o1 = 0.f;
    const int cl = (lane & 3) * 2;

    for (int jt = 0; jt < NJT; jt++) {
        int b = jt & 1;
        __syncthreads();  // all warps done reading buf b^1 (previous tile)
        if (jt + 1 < NJT) {
            uint32_t kb = sb + (b ^ 1) * KBUF;
            const __nv_bfloat16* sh = g_khi + (jt + 1) * BN * DD;
            const __nv_bfloat16* sl = g_klo + (jt + 1) * BN * DD;
#pragma unroll
            for (int t = 0; t < 8; t++) {
                int idx = t * 256 + tid;
                int r = idx >> 4, cu = idx & 15;
                uint32_t off = (uint32_t)r * 256u + (uint32_t)((cu ^ (r & 7)) << 4);
                CP_ASYNC16(kb + off,         sh + r * DD + cu * 8);
                CP_ASYNC16(kb + 32768 + off, sl + r * DD + cu * 8);
            }
            CP_COMMIT();
        }
        if (tid < 128) Us[tid] = 0.5f * g_u[jt * BN + tid];
        if (jt + 1 < NJT) CP_WAIT(1); else CP_WAIT(0);
        __syncthreads();

        uint32_t kb = sb + b * KBUF;
        float acc[16][4];
#pragma unroll
        for (int nb = 0; nb < 16; nb++) {
            acc[nb][0] = 0.f; acc[nb][1] = 0.f; acc[nb][2] = 0.f; acc[nb][3] = 0.f;
        }

#pragma unroll
        for (int kk = 0; kk < 8; kk++) {
            uint32_t coff = (uint32_t)(((kk * 2 + cB) ^ xB) << 4);
            uint32_t bh[8][4];
#pragma unroll
            for (int p = 0; p < 8; p++) ldsm4(bh[p], kb + p * 4096 + uB + coff);
#pragma unroll
            for (int p = 0; p < 8; p++) {
                mma_bf16(acc[2 * p], Ahi[kk], &bh[p][0]);
                mma_bf16(acc[2 * p + 1], Ahi[kk], &bh[p][2]);
            }
#pragma unroll
            for (int p = 0; p < 8; p++) {
                mma_bf16(acc[2 * p], Alo[kk], &bh[p][0]);
                mma_bf16(acc[2 * p + 1], Alo[kk], &bh[p][2]);
            }
#pragma unroll
            for (int p = 0; p < 8; p++) ldsm4(bh[p], kb + 32768 + p * 4096 + uB + coff);
#pragma unroll
            for (int p = 0; p < 8; p++) {
                mma_bf16(acc[2 * p], Ahi[kk], &bh[p][0]);
                mma_bf16(acc[2 * p + 1], Ahi[kk], &bh[p][2]);
            }
        }

        // sigmoid epilogue: sig = 0.5*tanh(0.5 s) + 0.5; o += sig*u
        // with uh = 0.5u:  o += uh*tanh(0.5 s) + uh  (uh-sum folded per tile)
        float ts = 0.f;
#pragma unroll
        for (int nb = 0; nb < 16; nb++) {
            float2 u2 = *(const float2*)(Us + nb * 8 + cl);
            ts += u2.x + u2.y;
            float t0 = tanh_ap(0.5f * acc[nb][0]);
            float t1 = tanh_ap(0.5f * acc[nb][1]);
            float t2 = tanh_ap(0.5f * acc[nb][2]);
            float t3 = tanh_ap(0.5f * acc[nb][3]);
            o0 = fmaf(t0, u2.x, o0); o0 = fmaf(t1, u2.y, o0);
            o1 = fmaf(t2, u2.x, o1); o1 = fmaf(t3, u2.y, o1);
        }
        o0 += ts;
        o1 += ts;
    }

    // reduce across the 4 lanes sharing each row
    o0 += __shfl_xor_sync(0xFFFFFFFFu, o0, 1);
    o0 += __shfl_xor_sync(0xFFFFFFFFu, o0, 2);
    o1 += __shfl_xor_sync(0xFFFFFFFFu, o1, 1);
    o1 += __shfl_xor_sync(0xFFFFFFFFu, o1, 2);
    if ((lane & 3) == 0) {
        int r = row0 + 16 * w + (lane >> 2);
        float bb = b_fc[0];
        out[r] = o0 + bb;
        out[r + 8] = o1 + bb;
    }
}

// ---------------- launch ----------------------------------------------
extern "C" void kernel_launch(void* const* d_in, const int* in_sizes, int n_in,
                              void* d_out, int out_size) {
    const float* x       = (const float*)d_in[0];
    const float* W_token = (const float*)d_in[2];
    const float* b_token = (const float*)d_in[3];
    const float* W_qkv   = (const float*)d_in[4];
    const float* b_qkv   = (const float*)d_in[5];
    const float* W_fc    = (const float*)d_in[6];
    const float* b_fc    = (const float*)d_in[7];
    float* out = (float*)d_out;

    cudaFuncSetAttribute(k_attn, cudaFuncAttributeMaxDynamicSharedMemorySize, AT_SMEM);

    k_p1<<<1, 128>>>(W_qkv, W_fc, b_qkv);
    k_p2<<<768, 256>>>(W_token, W_qkv);
    k_p3<<<1, 256>>>(b_token, W_qkv, b_qkv);
    k_proj<<<dim3(128, 2), 256>>>(x);
    k_u<<<NROWS / 8, 256>>>(x);
    k_attn<<<128, 256, AT_SMEM>>>(b_fc, out);
}

// round 7
// speedup vs baseline: 3.7548x; 1.3296x over previous
#include <cuda_runtime.h>
#include <cuda_fp16.h>
#include <cstdint>

#define NROWS 16384
#define INDIM 768
#define DD    128
#define BN    128
#define NJT   (NROWS / BN)

// ---------------- device scratch (no allocs allowed) ----------------
__device__ float g_wvfc[DD];
__device__ float g_bu_p;
__device__ float g_bu;
__device__ float g_wqk[INDIM * 256];
__device__ float g_wu[INDIM];
__device__ float g_bqk[256];
__device__ float g_u[NROWS];
__device__ __align__(16) __half g_xhi[NROWS * INDIM];
__device__ __align__(16) __half g_xlo[NROWS * INDIM];
__device__ __align__(16) __half g_wTh[256 * INDIM];
__device__ __align__(16) __half g_wTl[256 * INDIM];
__device__ __align__(16) __half g_qf[NROWS * DD];
__device__ __align__(16) __half g_khi[NROWS * DD];
__device__ __align__(16) __half g_klo[NROWS * DD];

// ---------------- PTX helpers (base ISA only) -------------------------
__device__ __forceinline__ uint32_t smem_u32(const void* p) {
    uint32_t a;
    asm("{ .reg .u64 t; cvta.to.shared.u64 t, %1; cvt.u32.u64 %0, t; }" : "=r"(a) : "l"(p));
    return a;
}
#define CP_ASYNC16(dst, src) asm volatile("cp.async.cg.shared.global [%0], [%1], 16;" :: "r"(dst), "l"(src) : "memory")
#define CP_COMMIT()          asm volatile("cp.async.commit_group;" ::: "memory")
#define CP_WAIT(n)           asm volatile("cp.async.wait_group %0;" :: "n"(n) : "memory")

__device__ __forceinline__ void ldsm4(uint32_t* r, uint32_t addr) {
    asm volatile("ldmatrix.sync.aligned.m8n8.x4.shared.b16 {%0,%1,%2,%3}, [%4];"
                 : "=r"(r[0]), "=r"(r[1]), "=r"(r[2]), "=r"(r[3]) : "r"(addr));
}
__device__ __forceinline__ void mma_f16(float* c, const uint32_t* a, const uint32_t* b) {
    asm volatile("mma.sync.aligned.m16n8k16.row.col.f32.f16.f16.f32 "
                 "{%0,%1,%2,%3}, {%4,%5,%6,%7}, {%8,%9}, {%0,%1,%2,%3};"
                 : "+f"(c[0]), "+f"(c[1]), "+f"(c[2]), "+f"(c[3])
                 : "r"(a[0]), "r"(a[1]), "r"(a[2]), "r"(a[3]), "r"(b[0]), "r"(b[1]));
}
__device__ __forceinline__ float tanh_ap(float x) {
    float r;
    asm("tanh.approx.f32 %0, %1;" : "=f"(r) : "f"(x));
    return r;
}

// ---------------- P1/P2/P3: tiny weight precompute --------------------
__global__ void k_p1(const float* __restrict__ W_qkv, const float* __restrict__ W_fc,
                     const float* __restrict__ b_qkv) {
    int d = threadIdx.x;
    float acc = 0.f;
    for (int e = 0; e < DD; e++) acc += W_qkv[d * 3 * DD + 2 * DD + e] * W_fc[e];
    g_wvfc[d] = acc;
    if (d == 0) {
        float b = 0.f;
        for (int e = 0; e < DD; e++) b += b_qkv[2 * DD + e] * W_fc[e];
        g_bu_p = b;
    }
}
__global__ void k_p2(const float* __restrict__ W_token, const float* __restrict__ W_qkv) {
    __shared__ float wt[DD];
    int t = blockIdx.x, n = threadIdx.x;
    if (n < DD) wt[n] = W_token[t * DD + n];
    __syncthreads();
    float acc = 0.f;
    for (int d = 0; d < DD; d++) acc += wt[d] * W_qkv[d * 3 * DD + n];
    g_wqk[t * 256 + n] = acc;
    if (n == 0) {
        float a = 0.f;
        for (int d = 0; d < DD; d++) a += wt[d] * g_wvfc[d];
        g_wu[t] = a;
    }
}
__global__ void k_p3(const float* __restrict__ b_token, const float* __restrict__ W_qkv,
                     const float* __restrict__ b_qkv) {
    int n = threadIdx.x;
    float acc = 0.f;
    for (int d = 0; d < DD; d++) acc += b_token[d] * W_qkv[d * 3 * DD + n];
    g_bqk[n] = acc + b_qkv[n];
    if (n == 0) {
        float a = 0.f;
        for (int d = 0; d < DD; d++) a += b_token[d] * g_wvfc[d];
        g_bu = a + g_bu_p;
    }
}
// transpose + fp16 hi/lo split of fused weight  (256 blocks, 768 threads)
__global__ void k_p2t() {
    int n = blockIdx.x, t = threadIdx.x;
    float v = g_wqk[t * 256 + n];
    __half h = __float2half_rn(v);
    g_wTh[n * INDIM + t] = h;
    g_wTl[n * INDIM + t] = __float2half_rn(v - __half2float(h));
}
// x -> fp16 hi/lo split (8 floats per thread)
__global__ __launch_bounds__(256) void k_split(const float* __restrict__ x) {
    long i = ((long)blockIdx.x * 256 + threadIdx.x) * 8;
#pragma unroll
    for (int p = 0; p < 2; p++) {
        float4 v = *(const float4*)(x + i + p * 4);
        __half2 h0 = __floats2half2_rn(v.x, v.y);
        __half2 h1 = __floats2half2_rn(v.z, v.w);
        __half2 l0 = __floats2half2_rn(v.x - __half2float(h0.x), v.y - __half2float(h0.y));
        __half2 l1 = __floats2half2_rn(v.z - __half2float(h1.x), v.w - __half2float(h1.y));
        *(__half2*)(g_xhi + i + p * 4) = h0;
        *(__half2*)(g_xhi + i + p * 4 + 2) = h1;
        *(__half2*)(g_xlo + i + p * 4) = l0;
        *(__half2*)(g_xlo + i + p * 4 + 2) = l1;
    }
}

// ---------------- projection GEMM (HMMA fp16 3-pass) -------------------
// [16384,768]@[768,128] per half. BM=128, BN=128, BK=64. Tiles 128r x 128B,
// 16B units XOR-swizzled by (r&7). Stage = xh|xl|wh|wl (16KB each), 2 stages.
#define PJ_SMEM 131072
__global__ __launch_bounds__(256, 1) void k_projh() {
    extern __shared__ char smem[];
    uint32_t sb = smem_u32(smem);
    int tid = threadIdx.x, lane = tid & 31, w = tid >> 5;
    int row0 = blockIdx.x * 128;
    int half = blockIdx.y;
    const __half* wh = g_wTh + (long)half * 128 * INDIM;
    const __half* wl = g_wTl + (long)half * 128 * INDIM;

#define PJ_LOAD(buf, kc)                                                          \
    do {                                                                          \
        uint32_t base_ = sb + (buf) * 65536;                                      \
        _Pragma("unroll")                                                         \
        for (int t_ = 0; t_ < 4; t_++) {                                          \
            int idx_ = t_ * 256 + tid;                                            \
            int r_ = idx_ >> 3, cu_ = idx_ & 7;                                   \
            uint32_t off_ = (uint32_t)r_ * 128u + (uint32_t)((cu_ ^ (r_ & 7)) << 4); \
            CP_ASYNC16(base_ + off_,         g_xhi + (long)(row0 + r_) * INDIM + (kc) + cu_ * 8); \
            CP_ASYNC16(base_ + 16384 + off_, g_xlo + (long)(row0 + r_) * INDIM + (kc) + cu_ * 8); \
            CP_ASYNC16(base_ + 32768 + off_, wh + (long)r_ * INDIM + (kc) + cu_ * 8); \
            CP_ASYNC16(base_ + 49152 + off_, wl + (long)r_ * INDIM + (kc) + cu_ * 8); \
        }                                                                         \
        CP_COMMIT();                                                              \
    } while (0)

    PJ_LOAD(0, 0);

    float acc[16][4];
#pragma unroll
    for (int nb = 0; nb < 16; nb++) {
        acc[nb][0] = 0.f; acc[nb][1] = 0.f; acc[nb][2] = 0.f; acc[nb][3] = 0.f;
    }

    int rA = 16 * w + (lane & 15);
    int cuA = lane >> 4;
    uint32_t rbA = (uint32_t)rA * 128u;
    int xA = rA & 7;
    int rB = (lane & 7) + ((lane & 16) >> 1);
    int cB = (lane >> 3) & 1;
    uint32_t uB = (uint32_t)rB * 128u;
    int xB = rB & 7;

    for (int s = 0; s < 12; s++) {
        if (s + 1 < 12) {
            PJ_LOAD((s + 1) & 1, (s + 1) * 64);
            CP_WAIT(1);
        } else {
            CP_WAIT(0);
        }
        __syncthreads();
        uint32_t base = sb + (s & 1) * 65536;
#pragma unroll
        for (int kk = 0; kk < 4; kk++) {
            uint32_t Ah[4], Al[4];
            uint32_t aoff = rbA + (uint32_t)(((kk * 2 + cuA) ^ xA) << 4);
            ldsm4(Ah, base + aoff);
            ldsm4(Al, base + 16384 + aoff);
            uint32_t coff = (uint32_t)(((kk * 2 + cB) ^ xB) << 4);
            uint32_t bh[8][4];
#pragma unroll
            for (int p = 0; p < 8; p++) ldsm4(bh[p], base + 32768 + p * 2048 + uB + coff);
#pragma unroll
            for (int p = 0; p < 8; p++) {
                mma_f16(acc[2 * p], Ah, &bh[p][0]);
                mma_f16(acc[2 * p + 1], Ah, &bh[p][2]);
            }
#pragma unroll
            for (int p = 0; p < 8; p++) {
                mma_f16(acc[2 * p], Al, &bh[p][0]);
                mma_f16(acc[2 * p + 1], Al, &bh[p][2]);
            }
#pragma unroll
            for (int p = 0; p < 8; p++) ldsm4(bh[p], base + 49152 + p * 2048 + uB + coff);
#pragma unroll
            for (int p = 0; p < 8; p++) {
                mma_f16(acc[2 * p], Ah, &bh[p][0]);
                mma_f16(acc[2 * p + 1], Ah, &bh[p][2]);
            }
        }
        __syncthreads();
    }

    // epilogue: +bias, q -> fp16 ; k -> fp16 hi/lo
    int r0 = row0 + 16 * w + (lane >> 2);
#pragma unroll
    for (int nb = 0; nb < 16; nb++) {
        int c = nb * 8 + (lane & 3) * 2;
        float b0 = g_bqk[half * 128 + c];
        float b1 = g_bqk[half * 128 + c + 1];
        float v0 = acc[nb][0] + b0, v1 = acc[nb][1] + b1;
        float v2 = acc[nb][2] + b0, v3 = acc[nb][3] + b1;
        if (half == 0) {
            *(__half2*)(g_qf + (long)r0 * DD + c) = __floats2half2_rn(v0, v1);
            *(__half2*)(g_qf + (long)(r0 + 8) * DD + c) = __floats2half2_rn(v2, v3);
        } else {
            __half h0 = __float2half_rn(v0), h1 = __float2half_rn(v1);
            __half h2 = __float2half_rn(v2), h3 = __float2half_rn(v3);
            *(__half2*)(g_khi + (long)r0 * DD + c) = __halves2half2(h0, h1);
            *(__half2*)(g_khi + (long)(r0 + 8) * DD + c) = __halves2half2(h2, h3);
            *(__half2*)(g_klo + (long)r0 * DD + c) =
                __floats2half2_rn(v0 - __half2float(h0), v1 - __half2float(h1));
            *(__half2*)(g_klo + (long)(r0 + 8) * DD + c) =
                __floats2half2_rn(v2 - __half2float(h2), v3 - __half2float(h3));
        }
    }
}

// ---------------- u matvec --------------------------------------------
__global__ void k_u(const float* __restrict__ x) {
    int w = (blockIdx.x * blockDim.x + threadIdx.x) >> 5;
    int lane = threadIdx.x & 31;
    if (w >= NROWS) return;
    const float* xr = x + (long)w * INDIM;
    float acc = 0.f;
    for (int t = lane; t < INDIM; t += 32) acc += xr[t] * g_wu[t];
#pragma unroll
    for (int off = 16; off; off >>= 1) acc += __shfl_xor_sync(0xFFFFFFFFu, acc, off);
    if (lane == 0) g_u[w] = acc + g_bu;
}

// ---------------- attention: HMMA fp16 2-pass QK^T + sigmoid ----------
// K buffers: khi 32KB + klo 32KB per buf, double buffered = 128KB.
// Q (single fp16) staged into buf1 then register-resident.
// Rows 256B, 16B units XOR-swizzled by (r&7).
#define KBUF   65536
#define SO_US  131072
#define AT_SMEM (SO_US + 512)

__global__ __launch_bounds__(256, 1) void k_attn(const float* __restrict__ b_fc,
                                                 float* __restrict__ out) {
    extern __shared__ char smem[];
    uint32_t sb = smem_u32(smem);
    int tid = threadIdx.x, lane = tid & 31, w = tid >> 5;
    int row0 = blockIdx.x * 128;
    float* Us = (float*)(smem + SO_US);

    // stage K tile 0 -> buf0, Q tile -> buf1
#pragma unroll
    for (int t = 0; t < 8; t++) {
        int idx = t * 256 + tid;
        int r = idx >> 4, cu = idx & 15;
        uint32_t off = (uint32_t)r * 256u + (uint32_t)((cu ^ (r & 7)) << 4);
        CP_ASYNC16(sb + off,         g_khi + (long)r * DD + cu * 8);
        CP_ASYNC16(sb + 32768 + off, g_klo + (long)r * DD + cu * 8);
        CP_ASYNC16(sb + KBUF + off,  g_qf + (long)(row0 + r) * DD + cu * 8);
    }
    CP_COMMIT();
    CP_WAIT(0);
    __syncthreads();

    // extract Q fragments (warp w owns rows 16w..16w+15)
    uint32_t Ah[8][4];
    {
        int rA = 16 * w + (lane & 15);
        int cuA = lane >> 4;
        uint32_t rb = (uint32_t)rA * 256u;
        int xA = rA & 7;
#pragma unroll
        for (int kk = 0; kk < 8; kk++) {
            uint32_t off = rb + (uint32_t)(((kk * 2 + cuA) ^ xA) << 4);
            ldsm4(Ah[kk], sb + KBUF + off);
        }
    }
    __syncthreads();  // Q staging area now reusable as K buf1

    int rB = (lane & 7) + ((lane & 16) >> 1);
    int cB = (lane >> 3) & 1;
    uint32_t uB = (uint32_t)rB * 256u;
    int xB = rB & 7;

    float o0 = 0.f, o1 = 0.f;
    const int cl = (lane & 3) * 2;

    for (int jt = 0; jt < NJT; jt++) {
        int b = jt & 1;
        __syncthreads();
        if (jt + 1 < NJT) {
            uint32_t kb = sb + (b ^ 1) * KBUF;
            const __half* sh = g_khi + (long)(jt + 1) * BN * DD;
            const __half* sl = g_klo + (long)(jt + 1) * BN * DD;
#pragma unroll
            for (int t = 0; t < 8; t++) {
                int idx = t * 256 + tid;
                int r = idx >> 4, cu = idx & 15;
                uint32_t off = (uint32_t)r * 256u + (uint32_t)((cu ^ (r & 7)) << 4);
                CP_ASYNC16(kb + off,         sh + (long)r * DD + cu * 8);
                CP_ASYNC16(kb + 32768 + off, sl + (long)r * DD + cu * 8);
            }
            CP_COMMIT();
        }
        if (tid < 128) Us[tid] = 0.5f * g_u[jt * BN + tid];
        if (jt + 1 < NJT) CP_WAIT(1); else CP_WAIT(0);
        __syncthreads();

        uint32_t kb = sb + b * KBUF;
        float acc[16][4];
#pragma unroll
        for (int nb = 0; nb < 16; nb++) {
            acc[nb][0] = 0.f; acc[nb][1] = 0.f; acc[nb][2] = 0.f; acc[nb][3] = 0.f;
        }

#pragma unroll
        for (int kk = 0; kk < 8; kk++) {
            uint32_t coff = (uint32_t)(((kk * 2 + cB) ^ xB) << 4);
            uint32_t bh[8][4];
#pragma unroll
            for (int p = 0; p < 8; p++) ldsm4(bh[p], kb + p * 4096 + uB + coff);
#pragma unroll
            for (int p = 0; p < 8; p++) {
                mma_f16(acc[2 * p], Ah[kk], &bh[p][0]);
                mma_f16(acc[2 * p + 1], Ah[kk], &bh[p][2]);
            }
#pragma unroll
            for (int p = 0; p < 8; p++) ldsm4(bh[p], kb + 32768 + p * 4096 + uB + coff);
#pragma unroll
            for (int p = 0; p < 8; p++) {
                mma_f16(acc[2 * p], Ah[kk], &bh[p][0]);
                mma_f16(acc[2 * p + 1], Ah[kk], &bh[p][2]);
            }
        }

        // sigmoid: sig = 0.5*tanh(0.5 s) + 0.5; with uh = 0.5u folded
        float ts = 0.f;
#pragma unroll
        for (int nb = 0; nb < 16; nb++) {
            float2 u2 = *(const float2*)(Us + nb * 8 + cl);
            ts += u2.x + u2.y;
            float t0 = tanh_ap(0.5f * acc[nb][0]);
            float t1 = tanh_ap(0.5f * acc[nb][1]);
            float t2 = tanh_ap(0.5f * acc[nb][2]);
            float t3 = tanh_ap(0.5f * acc[nb][3]);
            o0 = fmaf(t0, u2.x, o0); o0 = fmaf(t1, u2.y, o0);
            o1 = fmaf(t2, u2.x, o1); o1 = fmaf(t3, u2.y, o1);
        }
        o0 += ts;
        o1 += ts;
    }

    o0 += __shfl_xor_sync(0xFFFFFFFFu, o0, 1);
    o0 += __shfl_xor_sync(0xFFFFFFFFu, o0, 2);
    o1 += __shfl_xor_sync(0xFFFFFFFFu, o1, 1);
    o1 += __shfl_xor_sync(0xFFFFFFFFu, o1, 2);
    if ((lane & 3) == 0) {
        int r = row0 + 16 * w + (lane >> 2);
        float bb = b_fc[0];
        out[r] = o0 + bb;
        out[r + 8] = o1 + bb;
    }
}

// ---------------- launch ----------------------------------------------
extern "C" void kernel_launch(void* const* d_in, const int* in_sizes, int n_in,
                              void* d_out, int out_size) {
    const float* x       = (const float*)d_in[0];
    const float* W_token = (const float*)d_in[2];
    const float* b_token = (const float*)d_in[3];
    const float* W_qkv   = (const float*)d_in[4];
    const float* b_qkv   = (const float*)d_in[5];
    const float* W_fc    = (const float*)d_in[6];
    const float* b_fc    = (const float*)d_in[7];
    float* out = (float*)d_out;

    cudaFuncSetAttribute(k_attn, cudaFuncAttributeMaxDynamicSharedMemorySize, AT_SMEM);
    cudaFuncSetAttribute(k_projh, cudaFuncAttributeMaxDynamicSharedMemorySize, PJ_SMEM);

    k_p1<<<1, 128>>>(W_qkv, W_fc, b_qkv);
    k_p2<<<768, 256>>>(W_token, W_qkv);
    k_p3<<<1, 256>>>(b_token, W_qkv, b_qkv);
    k_p2t<<<256, 768>>>();
    k_split<<<NROWS * INDIM / (256 * 8), 256>>>(x);
    k_projh<<<dim3(128, 2), 256, PJ_SMEM>>>();
    k_u<<<NROWS / 8, 256>>>(x);
    k_attn<<<128, 256, AT_SMEM>>>(b_fc, out);
}

// round 10
// speedup vs baseline: 4.7871x; 1.2749x over previous
#include <cuda_runtime.h>
#include <cuda_fp16.h>
#include <cstdint>

#define NROWS 16384
#define INDIM 768
#define DD    128
#define BN    128
#define NJT   (NROWS / BN)
#define NITEMS (128 * NJT)

// ---------------- device scratch (no allocs allowed) ----------------
__device__ float g_wvfc[DD];
__device__ float g_bu_p;
__device__ float g_bu;
__device__ float g_wu[INDIM];
__device__ float g_bqk[256];
__device__ float g_u[NROWS];
__device__ __align__(16) __half g_xhi[NROWS * INDIM];
__device__ __align__(16) __half g_wTh[256 * INDIM];
__device__ __align__(16) __half g_wTl[256 * INDIM];
__device__ __align__(16) __half g_qf[NROWS * DD];
__device__ __align__(16) __half g_khi[NROWS * DD];
__device__ __align__(16) __half g_klo[NROWS * DD];

// ---------------- PTX helpers (base ISA only) -------------------------
__device__ __forceinline__ uint32_t smem_u32(const void* p) {
    uint32_t a;
    asm("{ .reg .u64 t; cvta.to.shared.u64 t, %1; cvt.u32.u64 %0, t; }" : "=r"(a) : "l"(p));
    return a;
}
#define CP_ASYNC16(dst, src) asm volatile("cp.async.cg.shared.global [%0], [%1], 16;" :: "r"(dst), "l"(src) : "memory")
#define CP_COMMIT()          asm volatile("cp.async.commit_group;" ::: "memory")
#define CP_WAIT(n)           asm volatile("cp.async.wait_group %0;" :: "n"(n) : "memory")

__device__ __forceinline__ void ldsm4(uint32_t* r, uint32_t addr) {
    asm volatile("ldmatrix.sync.aligned.m8n8.x4.shared.b16 {%0,%1,%2,%3}, [%4];"
                 : "=r"(r[0]), "=r"(r[1]), "=r"(r[2]), "=r"(r[3]) : "r"(addr));
}
__device__ __forceinline__ void mma_f16(float* c, const uint32_t* a, const uint32_t* b) {
    asm volatile("mma.sync.aligned.m16n8k16.row.col.f32.f16.f16.f32 "
                 "{%0,%1,%2,%3}, {%4,%5,%6,%7}, {%8,%9}, {%0,%1,%2,%3};"
                 : "+f"(c[0]), "+f"(c[1]), "+f"(c[2]), "+f"(c[3])
                 : "r"(a[0]), "r"(a[1]), "r"(a[2]), "r"(a[3]), "r"(b[0]), "r"(b[1]));
}
__device__ __forceinline__ float tanh_ap(float x) {
    float r;
    asm("tanh.approx.f32 %0, %1;" : "=f"(r) : "f"(x));
    return r;
}

// ---------------- P1/P2/P3: tiny weight precompute --------------------
__global__ void k_p1(const float* __restrict__ W_qkv, const float* __restrict__ W_fc,
                     const float* __restrict__ b_qkv) {
    int d = threadIdx.x;
    float acc = 0.f;
    for (int e = 0; e < DD; e++) acc += W_qkv[d * 3 * DD + 2 * DD + e] * W_fc[e];
    g_wvfc[d] = acc;
    if (d == 0) {
        float b = 0.f;
        for (int e = 0; e < DD; e++) b += b_qkv[2 * DD + e] * W_fc[e];
        g_bu_p = b;
    }
}
// fused weight: compute W_token@W_qkv[:, :256], store TRANSPOSED fp16 hi/lo
__global__ void k_p2(const float* __restrict__ W_token, const float* __restrict__ W_qkv) {
    __shared__ float wt[DD];
    int t = blockIdx.x, n = threadIdx.x;
    if (n < DD) wt[n] = W_token[t * DD + n];
    __syncthreads();
    float acc = 0.f;
    for (int d = 0; d < DD; d++) acc += wt[d] * W_qkv[d * 3 * DD + n];
    __half h = __float2half_rn(acc);
    g_wTh[n * INDIM + t] = h;
    g_wTl[n * INDIM + t] = __float2half_rn(acc - __half2float(h));
    if (n == 0) {
        float a = 0.f;
        for (int d = 0; d < DD; d++) a += wt[d] * g_wvfc[d];
        g_wu[t] = a;
    }
}
__global__ void k_p3(const float* __restrict__ b_token, const float* __restrict__ W_qkv,
                     const float* __restrict__ b_qkv) {
    int n = threadIdx.x;
    float acc = 0.f;
    for (int d = 0; d < DD; d++) acc += b_token[d] * W_qkv[d * 3 * DD + n];
    g_bqk[n] = acc + b_qkv[n];
    if (n == 0) {
        float a = 0.f;
        for (int d = 0; d < DD; d++) a += b_token[d] * g_wvfc[d];
        g_bu = a + g_bu_p;
    }
}

// ---------------- x -> fp16 hi split + u matvec (one warp per row) -----
__global__ __launch_bounds__(256) void k_xu(const float* __restrict__ x) {
    int row = blockIdx.x * 8 + (threadIdx.x >> 5);
    int lane = threadIdx.x & 31;
    const float* xr = x + (long)row * INDIM;
    __half* xh = g_xhi + (long)row * INDIM;
    float acc = 0.f;
#pragma unroll
    for (int i = 0; i < 6; i++) {
        int c = i * 128 + lane * 4;
        float4 v = *(const float4*)(xr + c);
        float4 wv = *(const float4*)(g_wu + c);
        acc += v.x * wv.x + v.y * wv.y + v.z * wv.z + v.w * wv.w;
        *(__half2*)(xh + c) = __floats2half2_rn(v.x, v.y);
        *(__half2*)(xh + c + 2) = __floats2half2_rn(v.z, v.w);
    }
#pragma unroll
    for (int off = 16; off; off >>= 1) acc += __shfl_xor_sync(0xFFFFFFFFu, acc, off);
    if (lane == 0) g_u[row] = acc + g_bu;
}

// ---------------- projection GEMM (HMMA fp16) --------------------------
// half 0 (q): 1 pass xh*wh.  half 1 (k): 2 passes xh*wh + xh*wl.
// BM=128, BN=128, BK=64. Stage: [xh 16K][wh 16K][wl 16K], double buffered.
#define PJ_STG  49152
#define PJ_SMEM (2 * PJ_STG)
__global__ __launch_bounds__(256, 1) void k_projh() {
    extern __shared__ char smem[];
    uint32_t sb = smem_u32(smem);
    int tid = threadIdx.x, lane = tid & 31, w = tid >> 5;
    int row0 = blockIdx.x * 128;
    int half = blockIdx.y;
    const __half* wh = g_wTh + (long)half * 128 * INDIM;
    const __half* wl = g_wTl + (long)half * 128 * INDIM;

#define PJ_LOAD(buf, kc)                                                          \
    do {                                                                          \
        uint32_t base_ = sb + (buf) * PJ_STG;                                     \
        _Pragma("unroll")                                                         \
        for (int t_ = 0; t_ < 4; t_++) {                                          \
            int idx_ = t_ * 256 + tid;                                            \
            int r_ = idx_ >> 3, cu_ = idx_ & 7;                                   \
            uint32_t off_ = (uint32_t)r_ * 128u + (uint32_t)((cu_ ^ (r_ & 7)) << 4); \
            CP_ASYNC16(base_ + off_,         g_xhi + (long)(row0 + r_) * INDIM + (kc) + cu_ * 8); \
            CP_ASYNC16(base_ + 16384 + off_, wh + (long)r_ * INDIM + (kc) + cu_ * 8); \
            if (half) CP_ASYNC16(base_ + 32768 + off_, wl + (long)r_ * INDIM + (kc) + cu_ * 8); \
        }                                                                         \
        CP_COMMIT();                                                              \
    } while (0)

    PJ_LOAD(0, 0);

    float acc[16][4];
#pragma unroll
    for (int nb = 0; nb < 16; nb++) {
        acc[nb][0] = 0.f; acc[nb][1] = 0.f; acc[nb][2] = 0.f; acc[nb][3] = 0.f;
    }

    int rA = 16 * w + (lane & 15);
    int cuA = lane >> 4;
    uint32_t rbA = (uint32_t)rA * 128u;
    int xA = rA & 7;
    int rB = (lane & 7) + ((lane & 16) >> 1);
    int cB = (lane >> 3) & 1;
    uint32_t uB = (uint32_t)rB * 128u;
    int xB = rB & 7;

    for (int s = 0; s < 12; s++) {
        if (s + 1 < 12) {
            PJ_LOAD((s + 1) & 1, (s + 1) * 64);
            CP_WAIT(1);
        } else {
            CP_WAIT(0);
        }
        __syncthreads();
        uint32_t base = sb + (s & 1) * PJ_STG;
#pragma unroll
        for (int kk = 0; kk < 4; kk++) {
            uint32_t Ah[4];
            uint32_t aoff = rbA + (uint32_t)(((kk * 2 + cuA) ^ xA) << 4);
            ldsm4(Ah, base + aoff);
            uint32_t coff = (uint32_t)(((kk * 2 + cB) ^ xB) << 4);
            uint32_t bh[8][4];
#pragma unroll
            for (int p = 0; p < 8; p++) ldsm4(bh[p], base + 16384 + p * 2048 + uB + coff);
#pragma unroll
            for (int p = 0; p < 8; p++) {
                mma_f16(acc[2 * p], Ah, &bh[p][0]);
                mma_f16(acc[2 * p + 1], Ah, &bh[p][2]);
            }
            if (half) {
#pragma unroll
                for (int p = 0; p < 8; p++) ldsm4(bh[p], base + 32768 + p * 2048 + uB + coff);
#pragma unroll
                for (int p = 0; p < 8; p++) {
                    mma_f16(acc[2 * p], Ah, &bh[p][0]);
                    mma_f16(acc[2 * p + 1], Ah, &bh[p][2]);
                }
            }
        }
        __syncthreads();
    }

    // epilogue: +bias, q -> fp16 ; k -> fp16 hi/lo
    int r0 = row0 + 16 * w + (lane >> 2);
#pragma unroll
    for (int nb = 0; nb < 16; nb++) {
        int c = nb * 8 + (lane & 3) * 2;
        float b0 = g_bqk[half * 128 + c];
        float b1 = g_bqk[half * 128 + c + 1];
        float v0 = acc[nb][0] + b0, v1 = acc[nb][1] + b1;
        float v2 = acc[nb][2] + b0, v3 = acc[nb][3] + b1;
        if (half == 0) {
            *(__half2*)(g_qf + (long)r0 * DD + c) = __floats2half2_rn(v0, v1);
            *(__half2*)(g_qf + (long)(r0 + 8) * DD + c) = __floats2half2_rn(v2, v3);
        } else {
            __half h0 = __float2half_rn(v0), h1 = __float2half_rn(v1);
            __half h2 = __float2half_rn(v2), h3 = __float2half_rn(v3);
            *(__half2*)(g_khi + (long)r0 * DD + c) = __halves2half2(h0, h1);
            *(__half2*)(g_khi + (long)(r0 + 8) * DD + c) = __halves2half2(h2, h3);
            *(__half2*)(g_klo + (long)r0 * DD + c) =
                __floats2half2_rn(v0 - __half2float(h0), v1 - __half2float(h1));
            *(__half2*)(g_klo + (long)(r0 + 8) * DD + c) =
                __floats2half2_rn(v2 - __half2float(h2), v3 - __half2float(h3));
        }
    }
}

// ---------------- out = b_fc (attention accumulates atomically) --------
__global__ void k_zero(const float* __restrict__ b_fc, float* __restrict__ out) {
    out[blockIdx.x * 256 + threadIdx.x] = b_fc[0];
}

// ---------------- attention: persistent HMMA fp16 2-pass + sigmoid -----
// Work items = (it, jt) flattened, statically partitioned over gridDim.x CTAs.
// K double buffered (khi 32K + klo 32K per buf). Q frags via direct LDG.
#define KBUF   65536
#define SO_US  131072
#define AT_SMEM (SO_US + 512)

__global__ __launch_bounds__(256, 1) void k_attn(float* __restrict__ out) {
    extern __shared__ char smem[];
    uint32_t sb = smem_u32(smem);
    int tid = threadIdx.x, lane = tid & 31, w = tid >> 5;
    float* Us = (float*)(smem + SO_US);

    int start = (int)((long)blockIdx.x * NITEMS / gridDim.x);
    int end = (int)((long)(blockIdx.x + 1) * NITEMS / gridDim.x);

    // preload K tile for first item into buf 0
    {
        int jt = start & (NJT - 1);
        const __half* sh = g_khi + (long)jt * BN * DD;
        const __half* sl = g_klo + (long)jt * BN * DD;
#pragma unroll
        for (int t = 0; t < 8; t++) {
            int idx = t * 256 + tid;
            int r = idx >> 4, cu = idx & 15;
            uint32_t off = (uint32_t)r * 256u + (uint32_t)((cu ^ (r & 7)) << 4);
            CP_ASYNC16(sb + off,         sh + (long)r * DD + cu * 8);
            CP_ASYNC16(sb + 32768 + off, sl + (long)r * DD + cu * 8);
        }
        CP_COMMIT();
    }

    int rB = (lane & 7) + ((lane & 16) >> 1);
    int cB = (lane >> 3) & 1;
    uint32_t uB = (uint32_t)rB * 256u;
    int xB = rB & 7;
    const int cl = (lane & 3) * 2;

    uint32_t Ah[8][4];
    float o0 = 0.f, o1 = 0.f;
    int it = -1;

    for (int idx = start; idx < end; idx++) {
        int b = (idx - start) & 1;
        int jt = idx & (NJT - 1);
        __syncthreads();  // all warps done with buf b^1 + Us
        if (idx + 1 < end) {
            int jn = (idx + 1) & (NJT - 1);
            uint32_t kb = sb + (b ^ 1) * KBUF;
            const __half* sh = g_khi + (long)jn * BN * DD;
            const __half* sl = g_klo + (long)jn * BN * DD;
#pragma unroll
            for (int t = 0; t < 8; t++) {
                int i2 = t * 256 + tid;
                int r = i2 >> 4, cu = i2 & 15;
                uint32_t off = (uint32_t)r * 256u + (uint32_t)((cu ^ (r & 7)) << 4);
                CP_ASYNC16(kb + off,         sh + (long)r * DD + cu * 8);
                CP_ASYNC16(kb + 32768 + off, sl + (long)r * DD + cu * 8);
            }
            CP_COMMIT();
        }
        if (tid < 128) Us[tid] = 0.5f * g_u[jt * BN + tid];
        if (idx + 1 < end) CP_WAIT(1); else CP_WAIT(0);
        __syncthreads();

        if ((idx >> 7) != it) {
            // flush previous row-tile
            if (it >= 0) {
                o0 += __shfl_xor_sync(0xFFFFFFFFu, o0, 1);
                o0 += __shfl_xor_sync(0xFFFFFFFFu, o0, 2);
                o1 += __shfl_xor_sync(0xFFFFFFFFu, o1, 1);
                o1 += __shfl_xor_sync(0xFFFFFFFFu, o1, 2);
                if ((lane & 3) == 0) {
                    int r = it * 128 + 16 * w + (lane >> 2);
                    atomicAdd(out + r, o0);
                    atomicAdd(out + r + 8, o1);
                }
            }
            it = idx >> 7;
            o0 = 0.f; o1 = 0.f;
            // load Q fragments directly from gmem (A-frag lane mapping)
            const __half* qb = g_qf + ((long)it * 128 + 16 * w + (lane >> 2)) * DD + cl;
#pragma unroll
            for (int kk = 0; kk < 8; kk++) {
                Ah[kk][0] = *(const uint32_t*)(qb + kk * 16);
                Ah[kk][1] = *(const uint32_t*)(qb + 8 * DD + kk * 16);
                Ah[kk][2] = *(const uint32_t*)(qb + kk * 16 + 8);
                Ah[kk][3] = *(const uint32_t*)(qb + 8 * DD + kk * 16 + 8);
            }
        }

        uint32_t kb = sb + b * KBUF;
        float acc[16][4];
#pragma unroll
        for (int nb = 0; nb < 16; nb++) {
            acc[nb][0] = 0.f; acc[nb][1] = 0.f; acc[nb][2] = 0.f; acc[nb][3] = 0.f;
        }

#pragma unroll
        for (int kk = 0; kk < 8; kk++) {
            uint32_t coff = (uint32_t)(((kk * 2 + cB) ^ xB) << 4);
            uint32_t bh[8][4];
#pragma unroll
            for (int p = 0; p < 8; p++) ldsm4(bh[p], kb + p * 4096 + uB + coff);
#pragma unroll
            for (int p = 0; p < 8; p++) {
                mma_f16(acc[2 * p], Ah[kk], &bh[p][0]);
                mma_f16(acc[2 * p + 1], Ah[kk], &bh[p][2]);
            }
#pragma unroll
            for (int p = 0; p < 8; p++) ldsm4(bh[p], kb + 32768 + p * 4096 + uB + coff);
#pragma unroll
            for (int p = 0; p < 8; p++) {
                mma_f16(acc[2 * p], Ah[kk], &bh[p][0]);
                mma_f16(acc[2 * p + 1], Ah[kk], &bh[p][2]);
            }
        }

        // sigmoid: sig = 0.5*tanh(0.5 s) + 0.5, uh = 0.5u folded
        float ts = 0.f;
#pragma unroll
        for (int nb = 0; nb < 16; nb++) {
            float2 u2 = *(const float2*)(Us + nb * 8 + cl);
            ts += u2.x + u2.y;
            float t0 = tanh_ap(0.5f * acc[nb][0]);
            float t1 = tanh_ap(0.5f * acc[nb][1]);
            float t2 = tanh_ap(0.5f * acc[nb][2]);
            float t3 = tanh_ap(0.5f * acc[nb][3]);
            o0 = fmaf(t0, u2.x, o0); o0 = fmaf(t1, u2.y, o0);
            o1 = fmaf(t2, u2.x, o1); o1 = fmaf(t3, u2.y, o1);
        }
        o0 += ts;
        o1 += ts;
    }

    // final flush
    o0 += __shfl_xor_sync(0xFFFFFFFFu, o0, 1);
    o0 += __shfl_xor_sync(0xFFFFFFFFu, o0, 2);
    o1 += __shfl_xor_sync(0xFFFFFFFFu, o1, 1);
    o1 += __shfl_xor_sync(0xFFFFFFFFu, o1, 2);
    if (it >= 0 && (lane & 3) == 0) {
        int r = it * 128 + 16 * w + (lane >> 2);
        atomicAdd(out + r, o0);
        atomicAdd(out + r + 8, o1);
    }
}

// ---------------- launch ----------------------------------------------
extern "C" void kernel_launch(void* const* d_in, const int* in_sizes, int n_in,
                              void* d_out, int out_size) {
    const float* x       = (const float*)d_in[0];
    const float* W_token = (const float*)d_in[2];
    const float* b_token = (const float*)d_in[3];
    const float* W_qkv   = (const float*)d_in[4];
    const float* b_qkv   = (const float*)d_in[5];
    const float* W_fc    = (const float*)d_in[6];
    const float* b_fc    = (const float*)d_in[7];
    float* out = (float*)d_out;

    int nsm = 148;
    cudaDeviceGetAttribute(&nsm, cudaDevAttrMultiProcessorCount, 0);

    cudaFuncSetAttribute(k_attn, cudaFuncAttributeMaxDynamicSharedMemorySize, AT_SMEM);
    cudaFuncSetAttribute(k_projh, cudaFuncAttributeMaxDynamicSharedMemorySize, PJ_SMEM);

    k_p1<<<1, 128>>>(W_qkv, W_fc, b_qkv);
    k_p2<<<768, 256>>>(W_token, W_qkv);
    k_p3<<<1, 256>>>(b_token, W_qkv, b_qkv);
    k_xu<<<NROWS / 8, 256>>>(x);
    k_projh<<<dim3(128, 2), 256, PJ_SMEM>>>();
    k_zero<<<NROWS / 256, 256>>>(b_fc, out);
    k_attn<<<nsm, 256, AT_SMEM>>>(out);
}

// round 11
// speedup vs baseline: 7.7975x; 1.6289x over previous
#include <cuda_runtime.h>
#include <cuda_fp16.h>
#include <cstdint>

#define NROWS 16384
#define INDIM 768
#define DD    128
#define BN    128
#define NJT   (NROWS / BN)
#define NITEMS (128 * NJT)

// ---------------- device scratch (no allocs allowed) ----------------
__device__ float g_wvfc[DD];
__device__ float g_bu_p;
__device__ float g_bu;
__device__ float g_wu[INDIM];
__device__ float g_bqk[256];
__device__ float g_u[NROWS];   // stores 0.5*u (epilogue identity: sig*u = uh*tanh + uh)
__device__ __align__(16) __half g_xhi[NROWS * INDIM];
__device__ __align__(16) __half g_wTh[256 * INDIM];
__device__ __align__(16) __half g_qf[NROWS * DD];
__device__ __align__(16) __half g_kf[NROWS * DD];

// ---------------- PTX helpers (base ISA only) -------------------------
__device__ __forceinline__ uint32_t smem_u32(const void* p) {
    uint32_t a;
    asm("{ .reg .u64 t; cvta.to.shared.u64 t, %1; cvt.u32.u64 %0, t; }" : "=r"(a) : "l"(p));
    return a;
}
#define CP_ASYNC16(dst, src) asm volatile("cp.async.cg.shared.global [%0], [%1], 16;" :: "r"(dst), "l"(src) : "memory")
#define CP_COMMIT()          asm volatile("cp.async.commit_group;" ::: "memory")
#define CP_WAIT(n)           asm volatile("cp.async.wait_group %0;" :: "n"(n) : "memory")

__device__ __forceinline__ void ldsm4(uint32_t* r, uint32_t addr) {
    asm volatile("ldmatrix.sync.aligned.m8n8.x4.shared.b16 {%0,%1,%2,%3}, [%4];"
                 : "=r"(r[0]), "=r"(r[1]), "=r"(r[2]), "=r"(r[3]) : "r"(addr));
}
__device__ __forceinline__ void mma_f16(float* c, const uint32_t* a, const uint32_t* b) {
    asm volatile("mma.sync.aligned.m16n8k16.row.col.f32.f16.f16.f32 "
                 "{%0,%1,%2,%3}, {%4,%5,%6,%7}, {%8,%9}, {%0,%1,%2,%3};"
                 : "+f"(c[0]), "+f"(c[1]), "+f"(c[2]), "+f"(c[3])
                 : "r"(a[0]), "r"(a[1]), "r"(a[2]), "r"(a[3]), "r"(b[0]), "r"(b[1]));
}
__device__ __forceinline__ float tanh_ap(float x) {
    float r;
    asm("tanh.approx.f32 %0, %1;" : "=f"(r) : "f"(x));
    return r;
}

// ---------------- P1/P2/P3: tiny weight precompute --------------------
__global__ void k_p1(const float* __restrict__ W_qkv, const float* __restrict__ W_fc,
                     const float* __restrict__ b_qkv) {
    int d = threadIdx.x;
    float acc = 0.f;
    for (int e = 0; e < DD; e++) acc += W_qkv[d * 3 * DD + 2 * DD + e] * W_fc[e];
    g_wvfc[d] = acc;
    if (d == 0) {
        float b = 0.f;
        for (int e = 0; e < DD; e++) b += b_qkv[2 * DD + e] * W_fc[e];
        g_bu_p = b;
    }
}
// fused weight: W_token@W_qkv[:, :256], stored TRANSPOSED fp16
__global__ void k_p2(const float* __restrict__ W_token, const float* __restrict__ W_qkv) {
    __shared__ float wt[DD];
    int t = blockIdx.x, n = threadIdx.x;
    if (n < DD) wt[n] = W_token[t * DD + n];
    __syncthreads();
    float acc = 0.f;
    for (int d = 0; d < DD; d++) acc += wt[d] * W_qkv[d * 3 * DD + n];
    g_wTh[n * INDIM + t] = __float2half_rn(acc);
    if (n == 0) {
        float a = 0.f;
        for (int d = 0; d < DD; d++) a += wt[d] * g_wvfc[d];
        g_wu[t] = a;
    }
}
__global__ void k_p3(const float* __restrict__ b_token, const float* __restrict__ W_qkv,
                     const float* __restrict__ b_qkv) {
    int n = threadIdx.x;
    float acc = 0.f;
    for (int d = 0; d < DD; d++) acc += b_token[d] * W_qkv[d * 3 * DD + n];
    g_bqk[n] = acc + b_qkv[n];
    if (n == 0) {
        float a = 0.f;
        for (int d = 0; d < DD; d++) a += b_token[d] * g_wvfc[d];
        g_bu = a + g_bu_p;
    }
}

// ---------------- x -> fp16 split + u matvec (one warp per row) --------
__global__ __launch_bounds__(256) void k_xu(const float* __restrict__ x) {
    int row = blockIdx.x * 8 + (threadIdx.x >> 5);
    int lane = threadIdx.x & 31;
    const float* xr = x + (long)row * INDIM;
    __half* xh = g_xhi + (long)row * INDIM;
    float acc = 0.f;
#pragma unroll
    for (int i = 0; i < 6; i++) {
        int c = i * 128 + lane * 4;
        float4 v = *(const float4*)(xr + c);
        float4 wv = *(const float4*)(g_wu + c);
        acc += v.x * wv.x + v.y * wv.y + v.z * wv.z + v.w * wv.w;
        *(__half2*)(xh + c) = __floats2half2_rn(v.x, v.y);
        *(__half2*)(xh + c + 2) = __floats2half2_rn(v.z, v.w);
    }
#pragma unroll
    for (int off = 16; off; off >>= 1) acc += __shfl_xor_sync(0xFFFFFFFFu, acc, off);
    if (lane == 0) g_u[row] = 0.5f * (acc + g_bu);   // pre-fold the sigmoid 0.5
}

// ---------------- projection GEMM (HMMA fp16, 1 pass per half) ---------
// BM=128, BN=128, BK=64. Stage: [xh 16K][wh 16K], double buffered.
#define PJ_STG  32768
#define PJ_SMEM (2 * PJ_STG)
__global__ __launch_bounds__(256, 1) void k_projh() {
    extern __shared__ char smem[];
    uint32_t sb = smem_u32(smem);
    int tid = threadIdx.x, lane = tid & 31, w = tid >> 5;
    int row0 = blockIdx.x * 128;
    int half = blockIdx.y;
    const __half* wh = g_wTh + (long)half * 128 * INDIM;

#define PJ_LOAD(buf, kc)                                                          \
    do {                                                                          \
        uint32_t base_ = sb + (buf) * PJ_STG;                                     \
        _Pragma("unroll")                                                         \
        for (int t_ = 0; t_ < 4; t_++) {                                          \
            int idx_ = t_ * 256 + tid;                                            \
            int r_ = idx_ >> 3, cu_ = idx_ & 7;                                   \
            uint32_t off_ = (uint32_t)r_ * 128u + (uint32_t)((cu_ ^ (r_ & 7)) << 4); \
            CP_ASYNC16(base_ + off_,         g_xhi + (long)(row0 + r_) * INDIM + (kc) + cu_ * 8); \
            CP_ASYNC16(base_ + 16384 + off_, wh + (long)r_ * INDIM + (kc) + cu_ * 8); \
        }                                                                         \
        CP_COMMIT();                                                              \
    } while (0)

    PJ_LOAD(0, 0);

    float acc[16][4];
#pragma unroll
    for (int nb = 0; nb < 16; nb++) {
        acc[nb][0] = 0.f; acc[nb][1] = 0.f; acc[nb][2] = 0.f; acc[nb][3] = 0.f;
    }

    int rA = 16 * w + (lane & 15);
    int cuA = lane >> 4;
    uint32_t rbA = (uint32_t)rA * 128u;
    int xA = rA & 7;
    int rB = (lane & 7) + ((lane & 16) >> 1);
    int cB = (lane >> 3) & 1;
    uint32_t uB = (uint32_t)rB * 128u;
    int xB = rB & 7;

    for (int s = 0; s < 12; s++) {
        if (s + 1 < 12) {
            PJ_LOAD((s + 1) & 1, (s + 1) * 64);
            CP_WAIT(1);
        } else {
            CP_WAIT(0);
        }
        __syncthreads();
        uint32_t base = sb + (s & 1) * PJ_STG;
#pragma unroll
        for (int kk = 0; kk < 4; kk++) {
            uint32_t Ah[4];
            uint32_t aoff = rbA + (uint32_t)(((kk * 2 + cuA) ^ xA) << 4);
            ldsm4(Ah, base + aoff);
            uint32_t coff = (uint32_t)(((kk * 2 + cB) ^ xB) << 4);
            uint32_t bh[8][4];
#pragma unroll
            for (int p = 0; p < 8; p++) ldsm4(bh[p], base + 16384 + p * 2048 + uB + coff);
#pragma unroll
            for (int p = 0; p < 8; p++) {
                mma_f16(acc[2 * p], Ah, &bh[p][0]);
                mma_f16(acc[2 * p + 1], Ah, &bh[p][2]);
            }
        }
        __syncthreads();
    }

    // epilogue: +bias, store single fp16
    __half* dst = half ? g_kf : g_qf;
    int r0 = row0 + 16 * w + (lane >> 2);
#pragma unroll
    for (int nb = 0; nb < 16; nb++) {
        int c = nb * 8 + (lane & 3) * 2;
        float b0 = g_bqk[half * 128 + c];
        float b1 = g_bqk[half * 128 + c + 1];
        *(__half2*)(dst + (long)r0 * DD + c) = __floats2half2_rn(acc[nb][0] + b0, acc[nb][1] + b1);
        *(__half2*)(dst + (long)(r0 + 8) * DD + c) = __floats2half2_rn(acc[nb][2] + b0, acc[nb][3] + b1);
    }
}

// ---------------- out = b_fc (attention accumulates atomically) --------
__global__ void k_zero(const float* __restrict__ b_fc, float* __restrict__ out) {
    out[blockIdx.x * 256 + threadIdx.x] = b_fc[0];
}

// ---------------- attention: persistent HMMA fp16 1-pass + sigmoid -----
// K single fp16, double buffered 32KB each; u prefetched via cp.async too.
#define KBUF   32768
#define SO_US  65536
#define AT_SMEM (SO_US + 1024)

__global__ __launch_bounds__(256, 1) void k_attn(float* __restrict__ out) {
    extern __shared__ char smem[];
    uint32_t sb = smem_u32(smem);
    int tid = threadIdx.x, lane = tid & 31, w = tid >> 5;

    int start = (int)((long)blockIdx.x * NITEMS / gridDim.x);
    int end = (int)((long)(blockIdx.x + 1) * NITEMS / gridDim.x);

    // preload K tile + u for first item into buf 0
    {
        int jt = start & (NJT - 1);
        const __half* sh = g_kf + (long)jt * BN * DD;
#pragma unroll
        for (int t = 0; t < 8; t++) {
            int idx = t * 256 + tid;
            int r = idx >> 4, cu = idx & 15;
            uint32_t off = (uint32_t)r * 256u + (uint32_t)((cu ^ (r & 7)) << 4);
            CP_ASYNC16(sb + off, sh + (long)r * DD + cu * 8);
        }
        if (tid < 32) CP_ASYNC16(sb + SO_US + tid * 16, g_u + jt * BN + tid * 4);
        CP_COMMIT();
    }

    int rB = (lane & 7) + ((lane & 16) >> 1);
    int cB = (lane >> 3) & 1;
    uint32_t uB = (uint32_t)rB * 256u;
    int xB = rB & 7;
    const int cl = (lane & 3) * 2;

    uint32_t Ah[8][4];
    float o0 = 0.f, o1 = 0.f;
    int it = -1;

    for (int idx = start; idx < end; idx++) {
        int b = (idx - start) & 1;
        __syncthreads();  // all warps done with buf b^1 (prev tile)
        if (idx + 1 < end) {
            int jn = (idx + 1) & (NJT - 1);
            uint32_t kb = sb + (b ^ 1) * KBUF;
            const __half* sh = g_kf + (long)jn * BN * DD;
#pragma unroll
            for (int t = 0; t < 8; t++) {
                int i2 = t * 256 + tid;
                int r = i2 >> 4, cu = i2 & 15;
                uint32_t off = (uint32_t)r * 256u + (uint32_t)((cu ^ (r & 7)) << 4);
                CP_ASYNC16(kb + off, sh + (long)r * DD + cu * 8);
            }
            if (tid < 32) CP_ASYNC16(sb + SO_US + (b ^ 1) * 512 + tid * 16, g_u + jn * BN + tid * 4);
            CP_COMMIT();
            CP_WAIT(1);
        } else {
            CP_WAIT(0);
        }
        __syncthreads();

        if ((idx >> 7) != it) {
            if (it >= 0) {
                o0 += __shfl_xor_sync(0xFFFFFFFFu, o0, 1);
                o0 += __shfl_xor_sync(0xFFFFFFFFu, o0, 2);
                o1 += __shfl_xor_sync(0xFFFFFFFFu, o1, 1);
                o1 += __shfl_xor_sync(0xFFFFFFFFu, o1, 2);
                if ((lane & 3) == 0) {
                    int r = it * 128 + 16 * w + (lane >> 2);
                    atomicAdd(out + r, o0);
                    atomicAdd(out + r + 8, o1);
                }
            }
            it = idx >> 7;
            o0 = 0.f; o1 = 0.f;
            const __half* qb = g_qf + ((long)it * 128 + 16 * w + (lane >> 2)) * DD + cl;
#pragma unroll
            for (int kk = 0; kk < 8; kk++) {
                Ah[kk][0] = *(const uint32_t*)(qb + kk * 16);
                Ah[kk][1] = *(const uint32_t*)(qb + 8 * DD + kk * 16);
                Ah[kk][2] = *(const uint32_t*)(qb + kk * 16 + 8);
                Ah[kk][3] = *(const uint32_t*)(qb + 8 * DD + kk * 16 + 8);
            }
        }

        uint32_t kb = sb + b * KBUF;
        float acc[16][4];
#pragma unroll
        for (int nb = 0; nb < 16; nb++) {
            acc[nb][0] = 0.f; acc[nb][1] = 0.f; acc[nb][2] = 0.f; acc[nb][3] = 0.f;
        }

#pragma unroll
        for (int kk = 0; kk < 8; kk++) {
            uint32_t coff = (uint32_t)(((kk * 2 + cB) ^ xB) << 4);
            uint32_t bh[8][4];
#pragma unroll
            for (int p = 0; p < 8; p++) ldsm4(bh[p], kb + p * 4096 + uB + coff);
#pragma unroll
            for (int p = 0; p < 8; p++) {
                mma_f16(acc[2 * p], Ah[kk], &bh[p][0]);
                mma_f16(acc[2 * p + 1], Ah[kk], &bh[p][2]);
            }
        }

        // sigmoid: sig*u = uh*tanh(0.5 s) + uh, uh = 0.5u (pre-folded in g_u)
        const float* Us = (const float*)(smem + SO_US + b * 512);
        float ts = 0.f;
#pragma unroll
        for (int nb = 0; nb < 16; nb++) {
            float2 u2 = *(const float2*)(Us + nb * 8 + cl);
            ts += u2.x + u2.y;
            float t0 = tanh_ap(0.5f * acc[nb][0]);
            float t1 = tanh_ap(0.5f * acc[nb][1]);
            float t2 = tanh_ap(0.5f * acc[nb][2]);
            float t3 = tanh_ap(0.5f * acc[nb][3]);
            o0 = fmaf(t0, u2.x, o0); o0 = fmaf(t1, u2.y, o0);
            o1 = fmaf(t2, u2.x, o1); o1 = fmaf(t3, u2.y, o1);
        }
        o0 += ts;
        o1 += ts;
    }

    o0 += __shfl_xor_sync(0xFFFFFFFFu, o0, 1);
    o0 += __shfl_xor_sync(0xFFFFFFFFu, o0, 2);
    o1 += __shfl_xor_sync(0xFFFFFFFFu, o1, 1);
    o1 += __shfl_xor_sync(0xFFFFFFFFu, o1, 2);
    if (it >= 0 && (lane & 3) == 0) {
        int r = it * 128 + 16 * w + (lane >> 2);
        atomicAdd(out + r, o0);
        atomicAdd(out + r + 8, o1);
    }
}

// ---------------- launch ----------------------------------------------
extern "C" void kernel_launch(void* const* d_in, const int* in_sizes, int n_in,
                              void* d_out, int out_size) {
    const float* x       = (const float*)d_in[0];
    const float* W_token = (const float*)d_in[2];
    const float* b_token = (const float*)d_in[3];
    const float* W_qkv   = (const float*)d_in[4];
    const float* b_qkv   = (const float*)d_in[5];
    const float* W_fc    = (const float*)d_in[6];
    const float* b_fc    = (const float*)d_in[7];
    float* out = (float*)d_out;

    int nsm = 148;
    cudaDeviceGetAttribute(&nsm, cudaDevAttrMultiProcessorCount, 0);

    cudaFuncSetAttribute(k_attn, cudaFuncAttributeMaxDynamicSharedMemorySize, AT_SMEM);
    cudaFuncSetAttribute(k_projh, cudaFuncAttributeMaxDynamicSharedMemorySize, PJ_SMEM);

    k_p1<<<1, 128>>>(W_qkv, W_fc, b_qkv);
    k_p2<<<768, 256>>>(W_token, W_qkv);
    k_p3<<<1, 256>>>(b_token, W_qkv, b_qkv);
    k_xu<<<NROWS / 8, 256>>>(x);
    k_projh<<<dim3(128, 2), 256, PJ_SMEM>>>();
    k_zero<<<NROWS / 256, 256>>>(b_fc, out);
    k_attn<<<nsm, 256, AT_SMEM>>>(out);
}